// round 13
// baseline (speedup 1.0000x reference)
#include <cuda_runtime.h>
#include <cuda_fp16.h>
#include <cstdint>
#include <math.h>

#define T_STEPS 128
#define BATCH   256
#define OBSD    512
#define ENCD    256
#define HID     512
#define NACT    18
#define NTOT    (T_STEPS * BATCH)   // 32768

#define N_GROUPS 8
#define BLKS_PER_GROUP 16
#define BF_UINTS (12 * 32 * 32 * 2)          // 24576
#define AF_UINTS (32 * 2 * 32 * 4)           // 8192
#define SCAN_SMEM_UINTS (BF_UINTS + AF_UINTS)
#define SCAN_SMEM_BYTES (SCAN_SMEM_UINTS * 4)   // 131072

// ---------------- scratch (static device globals; no runtime allocation) ----
__device__ __half g_h1[(size_t)NTOT * ENCD];
__device__ __half g_h2[(size_t)NTOT * ENCD];
__device__ __half g_gx[(size_t)NTOT * 3 * HID];
__device__ float  g_hidden[(size_t)NTOT * HID];
__device__ float  g_bcomb[3 * HID];
__device__ unsigned g_barriers[N_GROUPS][32];   // 128B-padded per-group counters

// ---------------------------------------------------------------------------
__device__ __forceinline__ unsigned pack_h2(float lo, float hi) {
    __half2 h = __float22half2_rn(make_float2(lo, hi));
    return *(unsigned*)&h;
}

__device__ __forceinline__ float2 h2_to_f2(unsigned u) {
    return __half22float2(*(__half2*)&u);
}

__device__ __forceinline__ void mma_f16(float d[4], const unsigned a[4], const unsigned b[2]) {
    asm volatile(
        "mma.sync.aligned.m16n8k16.row.col.f32.f16.f16.f32 "
        "{%0,%1,%2,%3}, {%4,%5,%6,%7}, {%8,%9}, {%0,%1,%2,%3};"
        : "+f"(d[0]), "+f"(d[1]), "+f"(d[2]), "+f"(d[3])
        : "r"(a[0]), "r"(a[1]), "r"(a[2]), "r"(a[3]), "r"(b[0]), "r"(b[1]));
}

__device__ __forceinline__ void ldsm_x4(unsigned r[4], unsigned addr) {
    asm volatile(
        "ldmatrix.sync.aligned.m8n8.x4.shared.b16 {%0,%1,%2,%3}, [%4];"
        : "=r"(r[0]), "=r"(r[1]), "=r"(r[2]), "=r"(r[3]) : "r"(addr));
}

__device__ __forceinline__ float fast_sigmoid(float x) {
    return 1.f / (1.f + __expf(-x));
}
__device__ __forceinline__ float fast_tanh(float x) {
    float t = __expf(-2.f * x);
    return (1.f - t) / (1.f + t);
}

__global__ void init_kernel(const float* __restrict__ b_ih,
                            const float* __restrict__ b_hh)
{
    int i = blockIdx.x * 256 + threadIdx.x;
    if (i < N_GROUPS) g_barriers[i][0] = 0u;
    if (i < 3 * HID)
        g_bcomb[i] = b_ih[i] + ((i < 2 * HID) ? b_hh[i] : 0.f);
}

// ---------------------------------------------------------------------------
// C_half[M,Nc] = act(A[M,K] @ W[Nc,K]^T + bias), fp16 mma m16n8k16, fp32 accum.
// BM=128, BN=128, BK=16, 256 threads (8 warps, 2m x 4n), warptile 64x32.
// A may be fp32 (A_HALF=0) or fp16 (A_HALF=1). Output is fp16.
// ---------------------------------------------------------------------------
template <bool RELU, bool A_HALF>
__global__ __launch_bounds__(256)
void gemm_f16_kernel(const void* __restrict__ Ap,
                     const float* __restrict__ W,
                     const float* __restrict__ bias,
                     __half* __restrict__ C,
                     int M, int Nc, int K)
{
    __shared__ unsigned As_u[2][128][12];   // 48B row stride
    __shared__ unsigned Ws_u[2][128][12];

    const int tid  = threadIdx.x;
    const int warp = tid >> 5;
    const int lane = tid & 31;
    const int g    = lane >> 2;
    const int tg   = lane & 3;
    const int warp_m = (warp & 1) * 64;
    const int warp_n = (warp >> 1) * 32;
    const int row0 = blockIdx.y * 128;
    const int col0 = blockIdx.x * 128;

    float acc[4][4][4];
#pragma unroll
    for (int i = 0; i < 4; i++)
#pragma unroll
        for (int j = 0; j < 4; j++)
#pragma unroll
            for (int q = 0; q < 4; q++) acc[i][j][q] = 0.f;

    const unsigned as_base = (unsigned)__cvta_generic_to_shared(&As_u[0][0][0]);
    const unsigned ws_base = (unsigned)__cvta_generic_to_shared(&Ws_u[0][0][0]);
    const unsigned a_off = (unsigned)((warp_m + (lane & 7) + ((lane >> 3) & 1) * 8) * 48
                                      + (lane >> 4) * 16);
    const unsigned w_off = (unsigned)((warp_n + (lane & 7) + (lane >> 4) * 8) * 48
                                      + ((lane >> 3) & 1) * 16);

    const float*  Af32 = (const float*)Ap;
    const __half* Af16 = (const __half*)Ap;

    float4 ra32[2];
    uint2  ra16[2];
    float4 rw[2];
#pragma unroll
    for (int l = 0; l < 2; l++) {
        int i = tid + l * 256;
        if (A_HALF)
            ra16[l] = *(const uint2*)(Af16 + (size_t)(row0 + (i >> 2)) * K + (i & 3) * 4);
        else
            ra32[l] = *(const float4*)(Af32 + (size_t)(row0 + (i >> 2)) * K + (i & 3) * 4);
        rw[l] = *(const float4*)(W + (size_t)(col0 + (i >> 2)) * K + (i & 3) * 4);
    }

    const int nk = K / 16;
    for (int kt = 0; kt < nk; kt++) {
        const int buf = kt & 1;
#pragma unroll
        for (int l = 0; l < 2; l++) {
            int i = tid + l * 256;
            int r = i >> 2, cu = (i & 3) * 2;
            if (A_HALF)
                *(uint2*)&As_u[buf][r][cu] = ra16[l];
            else
                *(uint2*)&As_u[buf][r][cu] =
                    make_uint2(pack_h2(ra32[l].x, ra32[l].y), pack_h2(ra32[l].z, ra32[l].w));
            *(uint2*)&Ws_u[buf][r][cu] =
                make_uint2(pack_h2(rw[l].x, rw[l].y), pack_h2(rw[l].z, rw[l].w));
        }
        __syncthreads();

        if (kt + 1 < nk) {
            int k0n = (kt + 1) * 16;
#pragma unroll
            for (int l = 0; l < 2; l++) {
                int i = tid + l * 256;
                if (A_HALF)
                    ra16[l] = *(const uint2*)(Af16 + (size_t)(row0 + (i >> 2)) * K + k0n + (i & 3) * 4);
                else
                    ra32[l] = *(const float4*)(Af32 + (size_t)(row0 + (i >> 2)) * K + k0n + (i & 3) * 4);
                rw[l] = *(const float4*)(W + (size_t)(col0 + (i >> 2)) * K + k0n + (i & 3) * 4);
            }
        }

        {
            const unsigned ab = as_base + (unsigned)(buf * 6144) + a_off;
            const unsigned wb = ws_base + (unsigned)(buf * 6144) + w_off;
            unsigned af[4][4], bq[2][4];
#pragma unroll
            for (int mf = 0; mf < 4; mf++) ldsm_x4(af[mf], ab + mf * 768);
#pragma unroll
            for (int q = 0; q < 2; q++) ldsm_x4(bq[q], wb + q * 768);
#pragma unroll
            for (int mf = 0; mf < 4; mf++) {
#pragma unroll
                for (int q = 0; q < 2; q++) {
                    unsigned bf0[2] = { bq[q][0], bq[q][1] };
                    unsigned bf1[2] = { bq[q][2], bq[q][3] };
                    mma_f16(acc[mf][q * 2 + 0], af[mf], bf0);
                    mma_f16(acc[mf][q * 2 + 1], af[mf], bf1);
                }
            }
        }
    }

#pragma unroll
    for (int mf = 0; mf < 4; mf++) {
#pragma unroll
        for (int nf = 0; nf < 4; nf++) {
            int r = row0 + warp_m + mf * 16 + g;
            int c = col0 + warp_n + nf * 8 + tg * 2;
            float b0v = bias[c], b1v = bias[c + 1];
            float v0 = acc[mf][nf][0] + b0v;
            float v1 = acc[mf][nf][1] + b1v;
            float v2 = acc[mf][nf][2] + b0v;
            float v3 = acc[mf][nf][3] + b1v;
            if (RELU) {
                v0 = fmaxf(v0, 0.f); v1 = fmaxf(v1, 0.f);
                v2 = fmaxf(v2, 0.f); v3 = fmaxf(v3, 0.f);
            }
            *(unsigned*)(C + (size_t)r * Nc + c)       = pack_h2(v0, v1);
            *(unsigned*)(C + (size_t)(r + 8) * Nc + c) = pack_h2(v2, v3);
        }
    }
}

// ---------------------------------------------------------------------------
// Persistent GRU scan, fp16 mma. 128 blocks = 8 groups x 16 tiles. gx is fp16.
// ---------------------------------------------------------------------------
__global__ __launch_bounds__(256)
void gru_scan_kernel(const float* __restrict__ gru_st,
                     const float* __restrict__ w_hh,
                     const float* __restrict__ b_hh,
                     const float* __restrict__ done,
                     float* __restrict__ out_state)
{
    extern __shared__ unsigned smu[];
    unsigned* Bf  = smu;                 // [nt(12)][k16(32)][lane(32)][2]
    unsigned* Afr = smu + BF_UINTS;      // [k16(32)][mt(2)][lane(32)][4]

    const int tid  = threadIdx.x;
    const int warp = tid >> 5;
    const int lane = tid & 31;
    const int g    = lane >> 2;
    const int tg   = lane & 3;
    const int bid  = blockIdx.x;
    const int col0 = (bid & 15) * 32;
    const int gid  = bid >> 4;
    const int row0 = gid * 32;
    const int mt_c = warp & 1;
    const int ntb  = warp >> 1;

    // ---- preload w_hh slice into fp16 fragment layout ----
    for (int i = tid; i < 96 * 32; i += 256) {
        int cr   = i >> 5;
        int k16c = i & 31;
        int gate = cr >> 5, lc = cr & 31;
        int nt = cr >> 3, gg = cr & 7;
        const float* wrow = w_hh + (size_t)(gate * HID + col0 + lc) * HID + k16c * 16;
        float4 w0 = *(const float4*)(wrow);
        float4 w1 = *(const float4*)(wrow + 4);
        float4 w2 = *(const float4*)(wrow + 8);
        float4 w3 = *(const float4*)(wrow + 12);
        unsigned* dst = Bf + (size_t)((nt * 32 + k16c) * 32 + gg * 4) * 2;
        *(uint4*)(dst)     = make_uint4(pack_h2(w0.x, w0.y), pack_h2(w2.x, w2.y),
                                        pack_h2(w0.z, w0.w), pack_h2(w2.z, w2.w));
        *(uint4*)(dst + 4) = make_uint4(pack_h2(w1.x, w1.y), pack_h2(w3.x, w3.y),
                                        pack_h2(w1.z, w1.w), pack_h2(w3.z, w3.w));
    }

    const int ccol = col0 + ntb * 8 + tg * 2;
    const float2 bn2 = *(const float2*)(b_hh + 2 * HID + ccol);

    const int r_a  = tid >> 3;
    const int c4a  = (tid & 7) * 4;
    const int kqo  = c4a >> 4;
    const int koff = c4a & 15;
    const int tg0  = (koff & 7) >> 1;
    const int mt_w = r_a >> 4, g_w = r_a & 7, half_w = (r_a >> 3) & 1;
    const int j_w  = half_w + ((koff >> 3) << 1);
    const int rr0  = mt_c * 16 + g;
    const int rr1  = rr0 + 8;

    __syncthreads();

    float m_a = 1.0f - __ldg(done + row0 + r_a);
    float m0  = 1.0f - __ldg(done + row0 + rr0);
    float m1  = 1.0f - __ldg(done + row0 + rr1);
    const __half* gx0p = g_gx + ((size_t)(row0 + rr0)) * (3 * HID);
    const __half* gx1p = g_gx + ((size_t)(row0 + rr1)) * (3 * HID);
    unsigned xr0 = *(const unsigned*)(gx0p + ccol);
    unsigned xz0 = *(const unsigned*)(gx0p + HID + ccol);
    unsigned xn0 = *(const unsigned*)(gx0p + 2 * HID + ccol);
    unsigned xr1 = *(const unsigned*)(gx1p + ccol);
    unsigned xz1 = *(const unsigned*)(gx1p + HID + ccol);
    unsigned xn1 = *(const unsigned*)(gx1p + 2 * HID + ccol);

    for (int t = 0; t < T_STEPS; t++) {
        const float* sin = (t == 0) ? gru_st
                                    : (g_hidden + (size_t)(t - 1) * BATCH * HID);
        float* sout = g_hidden + (size_t)t * BATCH * HID;

        const float* arow = sin + (size_t)(row0 + r_a) * HID;
        float4 ra[16];
#pragma unroll
        for (int kc = 0; kc < 16; kc++)
            ra[kc] = __ldcg((const float4*)(arow + kc * 32 + c4a));
        float2 hp0 = __ldcg((const float2*)(sin + (size_t)(row0 + rr0) * HID + ccol));
        float2 hp1 = __ldcg((const float2*)(sin + (size_t)(row0 + rr1) * HID + ccol));

#pragma unroll
        for (int kc = 0; kc < 16; kc++) {
            int kq = kc * 2 + kqo;
            unsigned* d = Afr + (size_t)((kq * 2 + mt_w) * 32 + g_w * 4 + tg0) * 4 + j_w;
            d[0] = pack_h2(ra[kc].x * m_a, ra[kc].y * m_a);
            d[4] = pack_h2(ra[kc].z * m_a, ra[kc].w * m_a);
        }
        __syncthreads();

        float acc[3][4];
#pragma unroll
        for (int gt = 0; gt < 3; gt++)
#pragma unroll
            for (int q = 0; q < 4; q++) acc[gt][q] = 0.f;

#pragma unroll 8
        for (int kq = 0; kq < 32; kq++) {
            uint4 av = *(const uint4*)(Afr + (size_t)((kq * 2 + mt_c) * 32 + lane) * 4);
            unsigned af[4] = { av.x, av.y, av.z, av.w };
#pragma unroll
            for (int gt = 0; gt < 3; gt++) {
                int nt = gt * 4 + ntb;
                uint2 bv = *(const uint2*)(Bf + (size_t)((nt * 32 + kq) * 32 + lane) * 2);
                unsigned bf[2] = { bv.x, bv.y };
                mma_f16(acc[gt], af, bf);
            }
        }

        {
            float2 fxr0 = h2_to_f2(xr0), fxz0 = h2_to_f2(xz0), fxn0 = h2_to_f2(xn0);
            float2 fxr1 = h2_to_f2(xr1), fxz1 = h2_to_f2(xz1), fxn1 = h2_to_f2(xn1);
            float r, z, n;
            r = fast_sigmoid(fxr0.x + acc[0][0]);
            z = fast_sigmoid(fxz0.x + acc[1][0]);
            n = fast_tanh(fxn0.x + r * (acc[2][0] + bn2.x));
            float hn0x = (1.f - z) * n + z * (hp0.x * m0);
            r = fast_sigmoid(fxr0.y + acc[0][1]);
            z = fast_sigmoid(fxz0.y + acc[1][1]);
            n = fast_tanh(fxn0.y + r * (acc[2][1] + bn2.y));
            float hn0y = (1.f - z) * n + z * (hp0.y * m0);
            r = fast_sigmoid(fxr1.x + acc[0][2]);
            z = fast_sigmoid(fxz1.x + acc[1][2]);
            n = fast_tanh(fxn1.x + r * (acc[2][2] + bn2.x));
            float hn1x = (1.f - z) * n + z * (hp1.x * m1);
            r = fast_sigmoid(fxr1.y + acc[0][3]);
            z = fast_sigmoid(fxz1.y + acc[1][3]);
            n = fast_tanh(fxn1.y + r * (acc[2][3] + bn2.y));
            float hn1y = (1.f - z) * n + z * (hp1.y * m1);

            float2 o0 = make_float2(hn0x, hn0y);
            float2 o1 = make_float2(hn1x, hn1y);
            *(float2*)(sout + (size_t)(row0 + rr0) * HID + ccol) = o0;
            *(float2*)(sout + (size_t)(row0 + rr1) * HID + ccol) = o1;
            if (t == T_STEPS - 1) {
                *(float2*)(out_state + (size_t)(row0 + rr0) * HID + ccol) = o0;
                *(float2*)(out_state + (size_t)(row0 + rr1) * HID + ccol) = o1;
            }
        }

        if (t < T_STEPS - 1) {
            m_a = 1.0f - __ldg(done + (t + 1) * BATCH + row0 + r_a);
            m0  = 1.0f - __ldg(done + (t + 1) * BATCH + row0 + rr0);
            m1  = 1.0f - __ldg(done + (t + 1) * BATCH + row0 + rr1);
            const __half* gx0 = g_gx + ((size_t)((t + 1) * BATCH + row0 + rr0)) * (3 * HID);
            const __half* gx1 = g_gx + ((size_t)((t + 1) * BATCH + row0 + rr1)) * (3 * HID);
            xr0 = *(const unsigned*)(gx0 + ccol);
            xz0 = *(const unsigned*)(gx0 + HID + ccol);
            xn0 = *(const unsigned*)(gx0 + 2 * HID + ccol);
            xr1 = *(const unsigned*)(gx1 + ccol);
            xz1 = *(const unsigned*)(gx1 + HID + ccol);
            xn1 = *(const unsigned*)(gx1 + 2 * HID + ccol);

            __threadfence();
            __syncthreads();
            if (tid == 0) {
                atomicAdd(&g_barriers[gid][0], 1u);
                unsigned target = (unsigned)BLKS_PER_GROUP * (unsigned)(t + 1);
                while (*(volatile unsigned*)&g_barriers[gid][0] < target) { }
                __threadfence();
            }
            __syncthreads();
        }
    }
}

// ---------------------------------------------------------------------------
// Heads: one warp per row n.
// ---------------------------------------------------------------------------
__global__ __launch_bounds__(256)
void heads_kernel(const int* __restrict__ action,
                  const float* __restrict__ w_actor,
                  const float* __restrict__ b_actor,
                  const float* __restrict__ w_critic,
                  const float* __restrict__ b_critic,
                  float* __restrict__ out)
{
    __shared__ float s_wa[NACT * HID];
    __shared__ float s_wc[HID];
    __shared__ float s_ba[NACT];

    const int tid = threadIdx.x;
    for (int i = tid; i < NACT * HID; i += 256) s_wa[i] = w_actor[i];
    for (int i = tid; i < HID; i += 256) s_wc[i] = w_critic[i];
    if (tid < NACT) s_ba[tid] = b_actor[tid];
    __syncthreads();

    const int warp = tid >> 5;
    const int lane = tid & 31;
    const int n = blockIdx.x * 8 + warp;

    const float* hrow = g_hidden + (size_t)n * HID;
    float h[16];
#pragma unroll
    for (int i = 0; i < 16; i++) h[i] = hrow[lane + 32 * i];

    float l[NACT];
#pragma unroll
    for (int a = 0; a < NACT; a++) {
        float p = 0.f;
        const float* wa = s_wa + a * HID;
#pragma unroll
        for (int i = 0; i < 16; i++) p += h[i] * wa[lane + 32 * i];
#pragma unroll
        for (int o = 16; o > 0; o >>= 1) p += __shfl_xor_sync(0xffffffffu, p, o);
        l[a] = p + s_ba[a];
    }

    float v = 0.f;
#pragma unroll
    for (int i = 0; i < 16; i++) v += h[i] * s_wc[lane + 32 * i];
#pragma unroll
    for (int o = 16; o > 0; o >>= 1) v += __shfl_xor_sync(0xffffffffu, v, o);
    v += b_critic[0];

    float mx = l[0];
#pragma unroll
    for (int a = 1; a < NACT; a++) mx = fmaxf(mx, l[a]);
    float s = 0.f;
#pragma unroll
    for (int a = 0; a < NACT; a++) s += expf(l[a] - mx);
    float lse = mx + logf(s);

    float ent = 0.f;
#pragma unroll
    for (int a = 0; a < NACT; a++) ent += expf(l[a] - lse) * (lse - l[a]);

    int act = action[n];
    float lp = 0.f;
#pragma unroll
    for (int a = 0; a < NACT; a++) lp += (a == act) ? (l[a] - lse) : 0.f;

    if (lane == 0) {
        out[n] = lp;
        out[NTOT + n] = ent;
        out[2 * NTOT + n] = v;
    }
}

// ---------------------------------------------------------------------------
extern "C" void kernel_launch(void* const* d_in, const int* in_sizes, int n_in,
                              void* d_out, int out_size)
{
    const float* x        = (const float*)d_in[0];
    const float* gru_st   = (const float*)d_in[1];
    const float* done     = (const float*)d_in[2];
    const int*   action   = (const int*)  d_in[3];
    const float* w1       = (const float*)d_in[4];
    const float* b1       = (const float*)d_in[5];
    const float* w2       = (const float*)d_in[6];
    const float* b2       = (const float*)d_in[7];
    const float* w_ih     = (const float*)d_in[8];
    const float* w_hh     = (const float*)d_in[9];
    const float* b_ih     = (const float*)d_in[10];
    const float* b_hh     = (const float*)d_in[11];
    const float* w_actor  = (const float*)d_in[12];
    const float* b_actor  = (const float*)d_in[13];
    const float* w_critic = (const float*)d_in[14];
    const float* b_critic = (const float*)d_in[15];
    float* out = (float*)d_out;

    __half *h1, *h2, *gx;
    float *bc;
    cudaGetSymbolAddress((void**)&h1, g_h1);
    cudaGetSymbolAddress((void**)&h2, g_h2);
    cudaGetSymbolAddress((void**)&gx, g_gx);
    cudaGetSymbolAddress((void**)&bc, g_bcomb);

    static int attrs_set = 0;
    if (!attrs_set) {
        cudaFuncSetAttribute(gru_scan_kernel,
                             cudaFuncAttributeMaxDynamicSharedMemorySize,
                             SCAN_SMEM_BYTES);
        attrs_set = 1;
    }

    // barriers + combined bias (b_ih + b_hh for r,z gates)
    init_kernel<<<(3 * HID + 255) / 256, 256>>>(b_ih, b_hh);

    // encoder layer 1: (N,512)@(512,256)^T -> h1 (fp16)
    gemm_f16_kernel<true, false><<<dim3(ENCD / 128, NTOT / 128), 256>>>(
        x, w1, b1, h1, NTOT, ENCD, OBSD);
    // encoder layer 2: (N,256)@(256,256)^T -> h2 (fp16, fp16 A)
    gemm_f16_kernel<true, true><<<dim3(ENCD / 128, NTOT / 128), 256>>>(
        h1, w2, b2, h2, NTOT, ENCD, ENCD);
    // input-side gates (bias = b_ih + b_hh[r,z]): (N,256)@(256,1536)^T -> gx (fp16)
    gemm_f16_kernel<false, true><<<dim3(3 * HID / 128, NTOT / 128), 256>>>(
        h2, w_ih, bc, gx, NTOT, 3 * HID, ENCD);

    // persistent GRU scan
    gru_scan_kernel<<<N_GROUPS * BLKS_PER_GROUP, 256, SCAN_SMEM_BYTES>>>(
        gru_st, w_hh, b_hh, done, out + 3 * NTOT);

    heads_kernel<<<NTOT / 8, 256>>>(action, w_actor, b_actor, w_critic, b_critic, out);
}

// round 14
// speedup vs baseline: 1.0673x; 1.0673x over previous
#include <cuda_runtime.h>
#include <cuda_fp16.h>
#include <cstdint>
#include <math.h>

#define T_STEPS 128
#define BATCH   256
#define OBSD    512
#define ENCD    256
#define HID     512
#define NACT    18
#define NTOT    (T_STEPS * BATCH)   // 32768

#define N_GROUPS 8
#define BLKS_PER_GROUP 16
#define BF_UINTS (12 * 32 * 32 * 2)          // 24576
#define AF_UINTS (32 * 2 * 32 * 4)           // 8192
#define SCAN_SMEM_UINTS (BF_UINTS + AF_UINTS)
#define SCAN_SMEM_BYTES (SCAN_SMEM_UINTS * 4)   // 131072

// ---------------- scratch (static device globals; no runtime allocation) ----
__device__ __half g_h1[(size_t)NTOT * ENCD];
__device__ __half g_h2[(size_t)NTOT * ENCD];
__device__ __half g_gx[(size_t)NTOT * 3 * HID];
__device__ __half g_hidden[(size_t)NTOT * HID];
__device__ float  g_bcomb[3 * HID];
__device__ unsigned g_barriers[N_GROUPS][32];   // 128B-padded per-group counters

// ---------------------------------------------------------------------------
__device__ __forceinline__ unsigned pack_h2(float lo, float hi) {
    __half2 h = __float22half2_rn(make_float2(lo, hi));
    return *(unsigned*)&h;
}

__device__ __forceinline__ float2 h2_to_f2(unsigned u) {
    return __half22float2(*(__half2*)&u);
}

__device__ __forceinline__ unsigned hmul2_u(unsigned a, unsigned m) {
    __half2 r = __hmul2(*(__half2*)&a, *(__half2*)&m);
    return *(unsigned*)&r;
}

__device__ __forceinline__ void mma_f16(float d[4], const unsigned a[4], const unsigned b[2]) {
    asm volatile(
        "mma.sync.aligned.m16n8k16.row.col.f32.f16.f16.f32 "
        "{%0,%1,%2,%3}, {%4,%5,%6,%7}, {%8,%9}, {%0,%1,%2,%3};"
        : "+f"(d[0]), "+f"(d[1]), "+f"(d[2]), "+f"(d[3])
        : "r"(a[0]), "r"(a[1]), "r"(a[2]), "r"(a[3]), "r"(b[0]), "r"(b[1]));
}

__device__ __forceinline__ void ldsm_x4(unsigned r[4], unsigned addr) {
    asm volatile(
        "ldmatrix.sync.aligned.m8n8.x4.shared.b16 {%0,%1,%2,%3}, [%4];"
        : "=r"(r[0]), "=r"(r[1]), "=r"(r[2]), "=r"(r[3]) : "r"(addr));
}

__device__ __forceinline__ float fast_sigmoid(float x) {
    return 1.f / (1.f + __expf(-x));
}
__device__ __forceinline__ float fast_tanh(float x) {
    float t = __expf(-2.f * x);
    return (1.f - t) / (1.f + t);
}

__global__ void init_kernel(const float* __restrict__ b_ih,
                            const float* __restrict__ b_hh)
{
    int i = blockIdx.x * 256 + threadIdx.x;
    if (i < N_GROUPS) g_barriers[i][0] = 0u;
    if (i < 3 * HID)
        g_bcomb[i] = b_ih[i] + ((i < 2 * HID) ? b_hh[i] : 0.f);
}

// ---------------------------------------------------------------------------
// C_half[M,Nc] = act(A[M,K] @ W[Nc,K]^T + bias), fp16 mma m16n8k16, fp32 accum.
// BM=128, BN=128, BK=16, 256 threads (8 warps, 2m x 4n), warptile 64x32.
// ---------------------------------------------------------------------------
template <bool RELU, bool A_HALF>
__global__ __launch_bounds__(256)
void gemm_f16_kernel(const void* __restrict__ Ap,
                     const float* __restrict__ W,
                     const float* __restrict__ bias,
                     __half* __restrict__ C,
                     int M, int Nc, int K)
{
    __shared__ unsigned As_u[2][128][12];   // 48B row stride
    __shared__ unsigned Ws_u[2][128][12];

    const int tid  = threadIdx.x;
    const int warp = tid >> 5;
    const int lane = tid & 31;
    const int g    = lane >> 2;
    const int tg   = lane & 3;
    const int warp_m = (warp & 1) * 64;
    const int warp_n = (warp >> 1) * 32;
    const int row0 = blockIdx.y * 128;
    const int col0 = blockIdx.x * 128;

    float acc[4][4][4];
#pragma unroll
    for (int i = 0; i < 4; i++)
#pragma unroll
        for (int j = 0; j < 4; j++)
#pragma unroll
            for (int q = 0; q < 4; q++) acc[i][j][q] = 0.f;

    const unsigned as_base = (unsigned)__cvta_generic_to_shared(&As_u[0][0][0]);
    const unsigned ws_base = (unsigned)__cvta_generic_to_shared(&Ws_u[0][0][0]);
    const unsigned a_off = (unsigned)((warp_m + (lane & 7) + ((lane >> 3) & 1) * 8) * 48
                                      + (lane >> 4) * 16);
    const unsigned w_off = (unsigned)((warp_n + (lane & 7) + (lane >> 4) * 8) * 48
                                      + ((lane >> 3) & 1) * 16);

    const float*  Af32 = (const float*)Ap;
    const __half* Af16 = (const __half*)Ap;

    float4 ra32[2];
    uint2  ra16[2];
    float4 rw[2];
#pragma unroll
    for (int l = 0; l < 2; l++) {
        int i = tid + l * 256;
        if (A_HALF)
            ra16[l] = *(const uint2*)(Af16 + (size_t)(row0 + (i >> 2)) * K + (i & 3) * 4);
        else
            ra32[l] = *(const float4*)(Af32 + (size_t)(row0 + (i >> 2)) * K + (i & 3) * 4);
        rw[l] = *(const float4*)(W + (size_t)(col0 + (i >> 2)) * K + (i & 3) * 4);
    }

    const int nk = K / 16;
    for (int kt = 0; kt < nk; kt++) {
        const int buf = kt & 1;
#pragma unroll
        for (int l = 0; l < 2; l++) {
            int i = tid + l * 256;
            int r = i >> 2, cu = (i & 3) * 2;
            if (A_HALF)
                *(uint2*)&As_u[buf][r][cu] = ra16[l];
            else
                *(uint2*)&As_u[buf][r][cu] =
                    make_uint2(pack_h2(ra32[l].x, ra32[l].y), pack_h2(ra32[l].z, ra32[l].w));
            *(uint2*)&Ws_u[buf][r][cu] =
                make_uint2(pack_h2(rw[l].x, rw[l].y), pack_h2(rw[l].z, rw[l].w));
        }
        __syncthreads();

        if (kt + 1 < nk) {
            int k0n = (kt + 1) * 16;
#pragma unroll
            for (int l = 0; l < 2; l++) {
                int i = tid + l * 256;
                if (A_HALF)
                    ra16[l] = *(const uint2*)(Af16 + (size_t)(row0 + (i >> 2)) * K + k0n + (i & 3) * 4);
                else
                    ra32[l] = *(const float4*)(Af32 + (size_t)(row0 + (i >> 2)) * K + k0n + (i & 3) * 4);
                rw[l] = *(const float4*)(W + (size_t)(col0 + (i >> 2)) * K + k0n + (i & 3) * 4);
            }
        }

        {
            const unsigned ab = as_base + (unsigned)(buf * 6144) + a_off;
            const unsigned wb = ws_base + (unsigned)(buf * 6144) + w_off;
            unsigned af[4][4], bq[2][4];
#pragma unroll
            for (int mf = 0; mf < 4; mf++) ldsm_x4(af[mf], ab + mf * 768);
#pragma unroll
            for (int q = 0; q < 2; q++) ldsm_x4(bq[q], wb + q * 768);
#pragma unroll
            for (int mf = 0; mf < 4; mf++) {
#pragma unroll
                for (int q = 0; q < 2; q++) {
                    unsigned bf0[2] = { bq[q][0], bq[q][1] };
                    unsigned bf1[2] = { bq[q][2], bq[q][3] };
                    mma_f16(acc[mf][q * 2 + 0], af[mf], bf0);
                    mma_f16(acc[mf][q * 2 + 1], af[mf], bf1);
                }
            }
        }
    }

#pragma unroll
    for (int mf = 0; mf < 4; mf++) {
#pragma unroll
        for (int nf = 0; nf < 4; nf++) {
            int r = row0 + warp_m + mf * 16 + g;
            int c = col0 + warp_n + nf * 8 + tg * 2;
            float b0v = bias[c], b1v = bias[c + 1];
            float v0 = acc[mf][nf][0] + b0v;
            float v1 = acc[mf][nf][1] + b1v;
            float v2 = acc[mf][nf][2] + b0v;
            float v3 = acc[mf][nf][3] + b1v;
            if (RELU) {
                v0 = fmaxf(v0, 0.f); v1 = fmaxf(v1, 0.f);
                v2 = fmaxf(v2, 0.f); v3 = fmaxf(v3, 0.f);
            }
            *(unsigned*)(C + (size_t)r * Nc + c)       = pack_h2(v0, v1);
            *(unsigned*)(C + (size_t)(r + 8) * Nc + c) = pack_h2(v2, v3);
        }
    }
}

// ---------------------------------------------------------------------------
// Persistent GRU scan, fp16 mma, fp16 state. 128 blocks = 8 groups x 16 tiles.
// Release/acquire spin barrier (no membar.gl).
// ---------------------------------------------------------------------------
__global__ __launch_bounds__(256)
void gru_scan_kernel(const float* __restrict__ gru_st,
                     const float* __restrict__ w_hh,
                     const float* __restrict__ b_hh,
                     const float* __restrict__ done,
                     float* __restrict__ out_state)
{
    extern __shared__ unsigned smu[];
    unsigned* Bf  = smu;                 // [nt(12)][k16(32)][lane(32)][2]
    unsigned* Afr = smu + BF_UINTS;      // [k16(32)][mt(2)][lane(32)][4]

    const int tid  = threadIdx.x;
    const int warp = tid >> 5;
    const int lane = tid & 31;
    const int g    = lane >> 2;
    const int tg   = lane & 3;
    const int bid  = blockIdx.x;
    const int col0 = (bid & 15) * 32;
    const int gid  = bid >> 4;
    const int row0 = gid * 32;
    const int mt_c = warp & 1;
    const int ntb  = warp >> 1;

    // ---- preload w_hh slice into fp16 fragment layout ----
    for (int i = tid; i < 96 * 32; i += 256) {
        int cr   = i >> 5;
        int k16c = i & 31;
        int gate = cr >> 5, lc = cr & 31;
        int nt = cr >> 3, gg = cr & 7;
        const float* wrow = w_hh + (size_t)(gate * HID + col0 + lc) * HID + k16c * 16;
        float4 w0 = *(const float4*)(wrow);
        float4 w1 = *(const float4*)(wrow + 4);
        float4 w2 = *(const float4*)(wrow + 8);
        float4 w3 = *(const float4*)(wrow + 12);
        unsigned* dst = Bf + (size_t)((nt * 32 + k16c) * 32 + gg * 4) * 2;
        *(uint4*)(dst)     = make_uint4(pack_h2(w0.x, w0.y), pack_h2(w2.x, w2.y),
                                        pack_h2(w0.z, w0.w), pack_h2(w2.z, w2.w));
        *(uint4*)(dst + 4) = make_uint4(pack_h2(w1.x, w1.y), pack_h2(w3.x, w3.y),
                                        pack_h2(w1.z, w1.w), pack_h2(w3.z, w3.w));
    }

    const int ccol = col0 + ntb * 8 + tg * 2;
    const float2 bn2 = *(const float2*)(b_hh + 2 * HID + ccol);

    const int r_a  = tid >> 3;
    const int c4a  = (tid & 7) * 4;      // element offset within 32-chunk
    const int kqo  = c4a >> 4;
    const int koff = c4a & 15;
    const int tg0  = (koff & 7) >> 1;
    const int mt_w = r_a >> 4, g_w = r_a & 7, half_w = (r_a >> 3) & 1;
    const int j_w  = half_w + ((koff >> 3) << 1);
    const int rr0  = mt_c * 16 + g;
    const int rr1  = rr0 + 8;

    unsigned* bar_addr = &g_barriers[gid][0];

    __syncthreads();

    float m_a = 1.0f - __ldg(done + row0 + r_a);
    float m0  = 1.0f - __ldg(done + row0 + rr0);
    float m1  = 1.0f - __ldg(done + row0 + rr1);
    const __half* gx0p = g_gx + ((size_t)(row0 + rr0)) * (3 * HID);
    const __half* gx1p = g_gx + ((size_t)(row0 + rr1)) * (3 * HID);
    unsigned xr0 = *(const unsigned*)(gx0p + ccol);
    unsigned xz0 = *(const unsigned*)(gx0p + HID + ccol);
    unsigned xn0 = *(const unsigned*)(gx0p + 2 * HID + ccol);
    unsigned xr1 = *(const unsigned*)(gx1p + ccol);
    unsigned xz1 = *(const unsigned*)(gx1p + HID + ccol);
    unsigned xn1 = *(const unsigned*)(gx1p + 2 * HID + ccol);

    for (int t = 0; t < T_STEPS; t++) {
        __half* sout = g_hidden + (size_t)t * BATCH * HID;

        // ---- load + stage h_prev (masked) into fragment layout ----
        float2 hp0, hp1;
        if (t == 0) {
            const float* arow = gru_st + (size_t)(row0 + r_a) * HID;
            float4 ra[16];
#pragma unroll
            for (int kc = 0; kc < 16; kc++)
                ra[kc] = __ldcg((const float4*)(arow + kc * 32 + c4a));
            hp0 = *(const float2*)(gru_st + (size_t)(row0 + rr0) * HID + ccol);
            hp1 = *(const float2*)(gru_st + (size_t)(row0 + rr1) * HID + ccol);
#pragma unroll
            for (int kc = 0; kc < 16; kc++) {
                int kq = kc * 2 + kqo;
                unsigned* d = Afr + (size_t)((kq * 2 + mt_w) * 32 + g_w * 4 + tg0) * 4 + j_w;
                d[0] = pack_h2(ra[kc].x * m_a, ra[kc].y * m_a);
                d[4] = pack_h2(ra[kc].z * m_a, ra[kc].w * m_a);
            }
        } else {
            const __half* sin = g_hidden + (size_t)(t - 1) * BATCH * HID;
            const __half* arow = sin + (size_t)(row0 + r_a) * HID;
            uint2 ra[16];
#pragma unroll
            for (int kc = 0; kc < 16; kc++)
                ra[kc] = __ldcg((const uint2*)(arow + kc * 32 + c4a));
            unsigned hp0u = *(const unsigned*)(sin + (size_t)(row0 + rr0) * HID + ccol);
            unsigned hp1u = *(const unsigned*)(sin + (size_t)(row0 + rr1) * HID + ccol);
            float2 f0 = h2_to_f2(hp0u), f1 = h2_to_f2(hp1u);
            hp0 = make_float2(f0.x, f0.y);
            hp1 = make_float2(f1.x, f1.y);
            const unsigned mh = pack_h2(m_a, m_a);
#pragma unroll
            for (int kc = 0; kc < 16; kc++) {
                int kq = kc * 2 + kqo;
                unsigned* d = Afr + (size_t)((kq * 2 + mt_w) * 32 + g_w * 4 + tg0) * 4 + j_w;
                d[0] = hmul2_u(ra[kc].x, mh);
                d[4] = hmul2_u(ra[kc].y, mh);
            }
        }
        __syncthreads();

        float acc[3][4];
#pragma unroll
        for (int gt = 0; gt < 3; gt++)
#pragma unroll
            for (int q = 0; q < 4; q++) acc[gt][q] = 0.f;

#pragma unroll 8
        for (int kq = 0; kq < 32; kq++) {
            uint4 av = *(const uint4*)(Afr + (size_t)((kq * 2 + mt_c) * 32 + lane) * 4);
            unsigned af[4] = { av.x, av.y, av.z, av.w };
#pragma unroll
            for (int gt = 0; gt < 3; gt++) {
                int nt = gt * 4 + ntb;
                uint2 bv = *(const uint2*)(Bf + (size_t)((nt * 32 + kq) * 32 + lane) * 2);
                unsigned bf[2] = { bv.x, bv.y };
                mma_f16(acc[gt], af, bf);
            }
        }

        {
            float2 fxr0 = h2_to_f2(xr0), fxz0 = h2_to_f2(xz0), fxn0 = h2_to_f2(xn0);
            float2 fxr1 = h2_to_f2(xr1), fxz1 = h2_to_f2(xz1), fxn1 = h2_to_f2(xn1);
            float r, z, n;
            r = fast_sigmoid(fxr0.x + acc[0][0]);
            z = fast_sigmoid(fxz0.x + acc[1][0]);
            n = fast_tanh(fxn0.x + r * (acc[2][0] + bn2.x));
            float hn0x = (1.f - z) * n + z * (hp0.x * m0);
            r = fast_sigmoid(fxr0.y + acc[0][1]);
            z = fast_sigmoid(fxz0.y + acc[1][1]);
            n = fast_tanh(fxn0.y + r * (acc[2][1] + bn2.y));
            float hn0y = (1.f - z) * n + z * (hp0.y * m0);
            r = fast_sigmoid(fxr1.x + acc[0][2]);
            z = fast_sigmoid(fxz1.x + acc[1][2]);
            n = fast_tanh(fxn1.x + r * (acc[2][2] + bn2.x));
            float hn1x = (1.f - z) * n + z * (hp1.x * m1);
            r = fast_sigmoid(fxr1.y + acc[0][3]);
            z = fast_sigmoid(fxz1.y + acc[1][3]);
            n = fast_tanh(fxn1.y + r * (acc[2][3] + bn2.y));
            float hn1y = (1.f - z) * n + z * (hp1.y * m1);

            *(unsigned*)(sout + (size_t)(row0 + rr0) * HID + ccol) = pack_h2(hn0x, hn0y);
            *(unsigned*)(sout + (size_t)(row0 + rr1) * HID + ccol) = pack_h2(hn1x, hn1y);
            if (t == T_STEPS - 1) {
                *(float2*)(out_state + (size_t)(row0 + rr0) * HID + ccol) =
                    make_float2(hn0x, hn0y);
                *(float2*)(out_state + (size_t)(row0 + rr1) * HID + ccol) =
                    make_float2(hn1x, hn1y);
            }
        }

        if (t < T_STEPS - 1) {
            // prefetch next step's pure inputs BEFORE the barrier spin
            m_a = 1.0f - __ldg(done + (t + 1) * BATCH + row0 + r_a);
            m0  = 1.0f - __ldg(done + (t + 1) * BATCH + row0 + rr0);
            m1  = 1.0f - __ldg(done + (t + 1) * BATCH + row0 + rr1);
            const __half* gx0 = g_gx + ((size_t)((t + 1) * BATCH + row0 + rr0)) * (3 * HID);
            const __half* gx1 = g_gx + ((size_t)((t + 1) * BATCH + row0 + rr1)) * (3 * HID);
            xr0 = *(const unsigned*)(gx0 + ccol);
            xz0 = *(const unsigned*)(gx0 + HID + ccol);
            xn0 = *(const unsigned*)(gx0 + 2 * HID + ccol);
            xr1 = *(const unsigned*)(gx1 + ccol);
            xz1 = *(const unsigned*)(gx1 + HID + ccol);
            xn1 = *(const unsigned*)(gx1 + 2 * HID + ccol);

            // release/acquire barrier (grid.sync pattern, no membar.gl)
            __syncthreads();
            if (tid == 0) {
                asm volatile("red.release.gpu.add.u32 [%0], %1;"
                             :: "l"(bar_addr), "r"(1u) : "memory");
                unsigned target = (unsigned)BLKS_PER_GROUP * (unsigned)(t + 1);
                unsigned v;
                do {
                    asm volatile("ld.acquire.gpu.u32 %0, [%1];"
                                 : "=r"(v) : "l"(bar_addr) : "memory");
                } while (v < target);
            }
            __syncthreads();
        }
    }
}

// ---------------------------------------------------------------------------
// Heads: one warp per row n (hidden is fp16 now).
// ---------------------------------------------------------------------------
__global__ __launch_bounds__(256)
void heads_kernel(const int* __restrict__ action,
                  const float* __restrict__ w_actor,
                  const float* __restrict__ b_actor,
                  const float* __restrict__ w_critic,
                  const float* __restrict__ b_critic,
                  float* __restrict__ out)
{
    __shared__ float s_wa[NACT * HID];
    __shared__ float s_wc[HID];
    __shared__ float s_ba[NACT];

    const int tid = threadIdx.x;
    for (int i = tid; i < NACT * HID; i += 256) s_wa[i] = w_actor[i];
    for (int i = tid; i < HID; i += 256) s_wc[i] = w_critic[i];
    if (tid < NACT) s_ba[tid] = b_actor[tid];
    __syncthreads();

    const int warp = tid >> 5;
    const int lane = tid & 31;
    const int n = blockIdx.x * 8 + warp;

    const __half* hrow = g_hidden + (size_t)n * HID;
    float h[16];
#pragma unroll
    for (int i = 0; i < 16; i++) h[i] = __half2float(hrow[lane + 32 * i]);

    float l[NACT];
#pragma unroll
    for (int a = 0; a < NACT; a++) {
        float p = 0.f;
        const float* wa = s_wa + a * HID;
#pragma unroll
        for (int i = 0; i < 16; i++) p += h[i] * wa[lane + 32 * i];
#pragma unroll
        for (int o = 16; o > 0; o >>= 1) p += __shfl_xor_sync(0xffffffffu, p, o);
        l[a] = p + s_ba[a];
    }

    float v = 0.f;
#pragma unroll
    for (int i = 0; i < 16; i++) v += h[i] * s_wc[lane + 32 * i];
#pragma unroll
    for (int o = 16; o > 0; o >>= 1) v += __shfl_xor_sync(0xffffffffu, v, o);
    v += b_critic[0];

    float mx = l[0];
#pragma unroll
    for (int a = 1; a < NACT; a++) mx = fmaxf(mx, l[a]);
    float s = 0.f;
#pragma unroll
    for (int a = 0; a < NACT; a++) s += expf(l[a] - mx);
    float lse = mx + logf(s);

    float ent = 0.f;
#pragma unroll
    for (int a = 0; a < NACT; a++) ent += expf(l[a] - lse) * (lse - l[a]);

    int act = action[n];
    float lp = 0.f;
#pragma unroll
    for (int a = 0; a < NACT; a++) lp += (a == act) ? (l[a] - lse) : 0.f;

    if (lane == 0) {
        out[n] = lp;
        out[NTOT + n] = ent;
        out[2 * NTOT + n] = v;
    }
}

// ---------------------------------------------------------------------------
extern "C" void kernel_launch(void* const* d_in, const int* in_sizes, int n_in,
                              void* d_out, int out_size)
{
    const float* x        = (const float*)d_in[0];
    const float* gru_st   = (const float*)d_in[1];
    const float* done     = (const float*)d_in[2];
    const int*   action   = (const int*)  d_in[3];
    const float* w1       = (const float*)d_in[4];
    const float* b1       = (const float*)d_in[5];
    const float* w2       = (const float*)d_in[6];
    const float* b2       = (const float*)d_in[7];
    const float* w_ih     = (const float*)d_in[8];
    const float* w_hh     = (const float*)d_in[9];
    const float* b_ih     = (const float*)d_in[10];
    const float* b_hh     = (const float*)d_in[11];
    const float* w_actor  = (const float*)d_in[12];
    const float* b_actor  = (const float*)d_in[13];
    const float* w_critic = (const float*)d_in[14];
    const float* b_critic = (const float*)d_in[15];
    float* out = (float*)d_out;

    __half *h1, *h2, *gx;
    float *bc;
    cudaGetSymbolAddress((void**)&h1, g_h1);
    cudaGetSymbolAddress((void**)&h2, g_h2);
    cudaGetSymbolAddress((void**)&gx, g_gx);
    cudaGetSymbolAddress((void**)&bc, g_bcomb);

    static int attrs_set = 0;
    if (!attrs_set) {
        cudaFuncSetAttribute(gru_scan_kernel,
                             cudaFuncAttributeMaxDynamicSharedMemorySize,
                             SCAN_SMEM_BYTES);
        attrs_set = 1;
    }

    // barriers + combined bias (b_ih + b_hh for r,z gates)
    init_kernel<<<(3 * HID + 255) / 256, 256>>>(b_ih, b_hh);

    // encoder layer 1: (N,512)@(512,256)^T -> h1 (fp16)
    gemm_f16_kernel<true, false><<<dim3(ENCD / 128, NTOT / 128), 256>>>(
        x, w1, b1, h1, NTOT, ENCD, OBSD);
    // encoder layer 2: (N,256)@(256,256)^T -> h2 (fp16, fp16 A)
    gemm_f16_kernel<true, true><<<dim3(ENCD / 128, NTOT / 128), 256>>>(
        h1, w2, b2, h2, NTOT, ENCD, ENCD);
    // input-side gates (bias = b_ih + b_hh[r,z]): (N,256)@(256,1536)^T -> gx (fp16)
    gemm_f16_kernel<false, true><<<dim3(3 * HID / 128, NTOT / 128), 256>>>(
        h2, w_ih, bc, gx, NTOT, 3 * HID, ENCD);

    // persistent GRU scan
    gru_scan_kernel<<<N_GROUPS * BLKS_PER_GROUP, 256, SCAN_SMEM_BYTES>>>(
        gru_st, w_hh, b_hh, done, out + 3 * NTOT);

    heads_kernel<<<NTOT / 8, 256>>>(action, w_actor, b_actor, w_critic, b_critic, out);
}